// round 1
// baseline (speedup 1.0000x reference)
#include <cuda_runtime.h>
#include <cuda_bf16.h>

// Problem constants (fixed-shape problem)
#define NB      32
#define NSITES  65536
#define NNGB    13
#define DIM     3
#define NG      48

// Scratch (device-global: allocation-free rule)
__device__ float g_InT[NSITES * NB];     // 8 MB, site-major transpose of In
__device__ float g_Wmean[DIM * NNGB];    // 39 floats

// ---------------------------------------------------------------------------
// Kernel 1: compute Wmean[d][j] = (1/48) * sum_g sum_{g',d'} gdiags[(g*3+d),(g'*3+d')]
//                                  * wtVC[d', GnnPerms[g', j]]
// ---------------------------------------------------------------------------
__global__ void prep_wmean_kernel(const float* __restrict__ wtVC,
                                  const float* __restrict__ gdiags,
                                  const int*   __restrict__ GnnPerms) {
    __shared__ float colsum[DIM * NG * DIM];   // [d][k], k = g'*3+d'  (432 floats)
    int tid = threadIdx.x;                     // 512 threads

    if (tid < DIM * NG * DIM) {
        int d = tid / (NG * DIM);
        int k = tid % (NG * DIM);
        float s = 0.f;
        #pragma unroll 8
        for (int g = 0; g < NG; g++)
            s += gdiags[(g * DIM + d) * (NG * DIM) + k];
        colsum[tid] = s * (1.0f / (float)NG);
    }
    __syncthreads();

    if (tid < DIM * NNGB) {
        int d = tid / NNGB;
        int j = tid % NNGB;
        float s = 0.f;
        for (int k = 0; k < NG * DIM; k++) {
            int gp = k / DIM;
            int dp = k % DIM;
            s += colsum[d * (NG * DIM) + k] * wtVC[dp * NNGB + GnnPerms[gp * NNGB + j]];
        }
        g_Wmean[tid] = s;
    }
}

// ---------------------------------------------------------------------------
// Kernel 2: transpose In (NB x NSITES) -> g_InT (NSITES x NB)
// 32x32 smem tiles, fully coalesced both directions.
// ---------------------------------------------------------------------------
__global__ void transpose_kernel(const float* __restrict__ In) {
    __shared__ float tile[32][33];
    int s0 = blockIdx.x * 32;
    int tx = threadIdx.x;   // 0..31
    int ty = threadIdx.y;   // 0..31

    // read: batch row ty, sites s0+tx  (coalesced over tx)
    tile[ty][tx] = In[ty * NSITES + s0 + tx];
    __syncthreads();
    // write: site s0+ty, batch tx  (coalesced over tx); tile[tx][ty] is conflict-free (pad 33)
    g_InT[(s0 + ty) * NB + tx] = tile[tx][ty];
}

// ---------------------------------------------------------------------------
// Kernel 3: main gather + contraction.
// Block = 32 consecutive sites. Warp w -> site s0+w, lane -> batch b.
// Each gather InT[idx*32 + lane] is one fully-used 128B line per warp.
// Output staged in padded smem, then written coalesced.
// ---------------------------------------------------------------------------
__global__ __launch_bounds__(1024, 2)
void conv_kernel(const int* __restrict__ NNsites, float* __restrict__ out) {
    __shared__ float Wm[40];              // 39 used
    __shared__ int   sidx[NNGB][32];      // indices for 32 sites
    __shared__ float sout[NB][DIM][33];   // padded: lane stride 99 words -> conflict-free

    int tid = threadIdx.x;                // 1024
    int s0  = blockIdx.x * 32;

    if (tid < DIM * NNGB) Wm[tid] = g_Wmean[tid];
    if (tid < NNGB * 32) {
        int j  = tid >> 5;
        int si = tid & 31;
        sidx[j][si] = NNsites[j * NSITES + s0 + si];   // coalesced over si
    }
    __syncthreads();

    int w    = tid >> 5;    // site within block (0..31)
    int lane = tid & 31;    // batch

    float a0 = 0.f, a1 = 0.f, a2 = 0.f;
    #pragma unroll
    for (int j = 0; j < NNGB; j++) {
        int   t = sidx[j][w];                        // broadcast LDS
        float v = g_InT[t * NB + lane];              // coalesced 128B line gather
        a0 += Wm[j]            * v;
        a1 += Wm[NNGB + j]     * v;
        a2 += Wm[2 * NNGB + j] * v;
    }
    sout[lane][0][w] = a0;
    sout[lane][1][w] = a1;
    sout[lane][2][w] = a2;
    __syncthreads();

    // Write out[b][d][s0 + si]: 3072 floats per block, 3 per thread.
    // Warp-aligned: within a warp (b,d) fixed, si = lane -> coalesced 128B stores,
    // smem reads consecutive -> conflict-free.
    #pragma unroll
    for (int k = 0; k < 3; k++) {
        int idx = tid + k * 1024;
        int b   = idx / 96;
        int r   = idx % 96;
        int d   = r >> 5;
        int si  = r & 31;
        out[(b * DIM + d) * NSITES + s0 + si] = sout[b][d][si];
    }
}

// ---------------------------------------------------------------------------
// Launch: In, wtVC, gdiags, GnnPerms, NNsites (metadata order)
// ---------------------------------------------------------------------------
extern "C" void kernel_launch(void* const* d_in, const int* in_sizes, int n_in,
                              void* d_out, int out_size) {
    const float* In       = (const float*)d_in[0];
    const float* wtVC     = (const float*)d_in[1];
    const float* gdiags   = (const float*)d_in[2];
    const int*   GnnPerms = (const int*)  d_in[3];
    const int*   NNsites  = (const int*)  d_in[4];
    float*       out      = (float*)d_out;

    prep_wmean_kernel<<<1, 512>>>(wtVC, gdiags, GnnPerms);

    dim3 tblk(32, 32);
    transpose_kernel<<<NSITES / 32, tblk>>>(In);

    conv_kernel<<<NSITES / 32, 1024>>>(NNsites, out);
}